// round 1
// baseline (speedup 1.0000x reference)
#include <cuda_runtime.h>
#include <cuda_bf16.h>
#include <math.h>

// Problem constants (VectorQuantizerEMA): D=64, K=512, N=B*T=262144.
#define DIM 64
#define NCODES 512
#define TPB 512
#define MAX_BLOCKS 4096

__device__ float g_w[NCODES];      // sqrt(ema_cluster_size)
__device__ float g_ee[NCODES];     // ||e_k||^2
__device__ float g_part[MAX_BLOCKS];

// ---------- packed f32x2 helpers ----------
static __device__ __forceinline__ unsigned long long f32x2_fma(
    unsigned long long a, unsigned long long b, unsigned long long c) {
    unsigned long long d;
    asm("fma.rn.f32x2 %0, %1, %2, %3;" : "=l"(d) : "l"(a), "l"(b), "l"(c));
    return d;
}
static __device__ __forceinline__ float2 u2f(unsigned long long u) {
    union { unsigned long long u; float2 f; } c;
    c.u = u;
    return c.f;
}

// ---------- kernel 1: per-code precompute ----------
__global__ void vq_pre(const float* __restrict__ emb,
                       const float* __restrict__ ema) {
    int k = blockIdx.x * blockDim.x + threadIdx.x;
    if (k < NCODES) {
        g_w[k] = sqrtf(ema[k]);
        const float* e = emb + k * DIM;
        float s = 0.f;
#pragma unroll
        for (int d = 0; d < DIM; d++) s += e[d] * e[d];
        g_ee[k] = s;
    }
}

// ---------- kernel 2: fused distance GEMM + argmin + quantize + loss partial ----------
__global__ void __launch_bounds__(TPB, 1)
vq_main(const float* __restrict__ inputs,
        const float* __restrict__ emb,
        float* __restrict__ out_q,
        float* __restrict__ out_idx,
        int N) {
    extern __shared__ float smem[];
    float* se  = smem;                    // [NCODES*DIM] codebook
    float* sw  = smem + NCODES * DIM;     // [NCODES]
    float* see = sw + NCODES;             // [NCODES]

    // cooperative load of codebook + per-code terms into smem
    {
        const float4* ev = (const float4*)emb;
        float4* sv = (float4*)se;
        for (int i = threadIdx.x; i < NCODES * DIM / 4; i += blockDim.x)
            sv[i] = ev[i];
        for (int i = threadIdx.x; i < NCODES; i += blockDim.x) {
            sw[i]  = g_w[i];
            see[i] = g_ee[i];
        }
    }
    __syncthreads();

    int n = blockIdx.x * blockDim.x + threadIdx.x;
    float lsum = 0.f;

    if (n < N) {
        // load x into registers, packed as 32 x f32x2 along D
        unsigned long long x2[DIM / 2];
        float xx = 0.f;
        {
            const ulonglong2* xp =
                (const ulonglong2*)(inputs + (size_t)n * DIM);
#pragma unroll
            for (int j = 0; j < DIM / 4; j++) {
                ulonglong2 v = xp[j];
                x2[2 * j]     = v.x;
                x2[2 * j + 1] = v.y;
                float2 a = u2f(v.x), b = u2f(v.y);
                xx += a.x * a.x + a.y * a.y + b.x * b.x + b.y * b.y;
            }
        }

        float best = INFINITY;
        int bestk = 0;

#pragma unroll 1
        for (int k = 0; k < NCODES; k += 2) {
            const ulonglong2* ea = (const ulonglong2*)(se + k * DIM);
            const ulonglong2* eb = (const ulonglong2*)(se + (k + 1) * DIM);
            unsigned long long aa0 = 0ull, aa1 = 0ull, ab0 = 0ull, ab1 = 0ull;
#pragma unroll
            for (int j = 0; j < DIM / 4; j++) {
                ulonglong2 va = ea[j];
                ulonglong2 vb = eb[j];
                aa0 = f32x2_fma(x2[2 * j],     va.x, aa0);
                aa1 = f32x2_fma(x2[2 * j + 1], va.y, aa1);
                ab0 = f32x2_fma(x2[2 * j],     vb.x, ab0);
                ab1 = f32x2_fma(x2[2 * j + 1], vb.y, ab1);
            }
            float2 A0 = u2f(aa0), A1 = u2f(aa1);
            float2 B0 = u2f(ab0), B1 = u2f(ab1);
            float da = (A0.x + A0.y) + (A1.x + A1.y);
            float db = (B0.x + B0.y) + (B1.x + B1.y);
            // same op order as reference: (xx + ee - 2*dot) * w
            float ta = (xx + see[k]     - 2.0f * da) * sw[k];
            float tb = (xx + see[k + 1] - 2.0f * db) * sw[k + 1];
            if (ta < best) { best = ta; bestk = k; }
            if (tb < best) { best = tb; bestk = k + 1; }
        }

        // write quantized = e[bestk], accumulate loss partial from registers
        {
            const float2* eb_ = (const float2*)(se + bestk * DIM);
            float2* oq = (float2*)(out_q + (size_t)n * DIM);
#pragma unroll
            for (int j = 0; j < DIM / 2; j++) {
                float2 ev = eb_[j];
                float2 xv = u2f(x2[j]);
                float dx = xv.x - ev.x;
                float dy = xv.y - ev.y;
                lsum += dx * dx + dy * dy;
                oq[j] = ev;
            }
            out_idx[n] = (float)bestk;
        }
    }

    // block reduction of loss partials (reuse smem after barrier)
    __syncthreads();
    float* red = smem;
    red[threadIdx.x] = lsum;
    __syncthreads();
#pragma unroll
    for (int s = TPB / 2; s > 0; s >>= 1) {
        if (threadIdx.x < s) red[threadIdx.x] += red[threadIdx.x + s];
        __syncthreads();
    }
    if (threadIdx.x == 0) g_part[blockIdx.x] = red[0];
}

// ---------- kernel 3: finalize loss ----------
__global__ void vq_finalize(float* __restrict__ out_loss, int nblocks,
                            float inv_count) {
    __shared__ float red[TPB];
    float s = 0.f;
    for (int i = threadIdx.x; i < nblocks; i += TPB) s += g_part[i];
    red[threadIdx.x] = s;
    __syncthreads();
#pragma unroll
    for (int st = TPB / 2; st > 0; st >>= 1) {
        if (threadIdx.x < st) red[threadIdx.x] += red[threadIdx.x + st];
        __syncthreads();
    }
    if (threadIdx.x == 0) out_loss[0] = 0.25f * red[0] * inv_count;
}

extern "C" void kernel_launch(void* const* d_in, const int* in_sizes, int n_in,
                              void* d_out, int out_size) {
    const float* inputs = (const float*)d_in[0];   // [B,T,D] f32
    const float* emb    = (const float*)d_in[1];   // [K,D]   f32
    const float* ema    = (const float*)d_in[2];   // [K]     f32

    int N = in_sizes[0] / DIM;                     // 262144
    float* out = (float*)d_out;
    // output layout: quantized_st [N*D], loss [1], indices [N]
    float* out_q    = out;
    float* out_loss = out + (size_t)N * DIM;
    float* out_idx  = out + (size_t)N * DIM + 1;

    size_t smem = (size_t)(NCODES * DIM + 2 * NCODES) * sizeof(float);
    static bool attr_done = false;
    if (!attr_done) {
        cudaFuncSetAttribute(vq_main, cudaFuncAttributeMaxDynamicSharedMemorySize,
                             (int)smem);
        attr_done = true;
    }

    int nblocks = (N + TPB - 1) / TPB;             // 512

    vq_pre<<<(NCODES + 127) / 128, 128>>>(emb, ema);
    vq_main<<<nblocks, TPB, smem>>>(inputs, emb, out_q, out_idx, N);
    vq_finalize<<<1, TPB>>>(out_loss, nblocks, 1.0f / ((float)N * (float)DIM));
}

// round 2
// speedup vs baseline: 1.3051x; 1.3051x over previous
#include <cuda_runtime.h>
#include <cuda_bf16.h>
#include <math.h>

// VectorQuantizerEMA: D=64, K=512, N=B*T=262144.
#define DIM 64
#define NCODES 512
#define TPB 256
#define GRID 152   // GB300: 152 SMs, 1 persistent CTA each (132KB smem -> occ 1)

__device__ float g_part[GRID];

// ---------- packed f32x2 helpers ----------
static __device__ __forceinline__ unsigned long long f32x2_fma(
    unsigned long long a, unsigned long long b, unsigned long long c) {
    unsigned long long d;
    asm("fma.rn.f32x2 %0, %1, %2, %3;" : "=l"(d) : "l"(a), "l"(b), "l"(c));
    return d;
}
static __device__ __forceinline__ float2 u2f(unsigned long long u) {
    union { unsigned long long u; float2 f; } c;
    c.u = u;
    return c.f;
}

// ---------- main: persistent fused distance GEMM + argmin + quantize + loss ----------
__global__ void __launch_bounds__(TPB, 1)
vq_main(const float* __restrict__ inputs,
        const float* __restrict__ emb,
        const float* __restrict__ ema,
        float* __restrict__ out_q,
        float* __restrict__ out_idx,
        int N) {
    extern __shared__ float smem[];
    float*  se  = smem;                         // [NCODES*DIM] codebook
    float2* wee = (float2*)(smem + NCODES * DIM); // [NCODES] (ee, w)

    // cooperative load of codebook
    {
        const float4* ev = (const float4*)emb;
        float4* sv = (float4*)se;
#pragma unroll 4
        for (int i = threadIdx.x; i < NCODES * DIM / 4; i += TPB)
            sv[i] = ev[i];
    }
    __syncthreads();
    // per-code precompute (fused; 2 codes per thread)
    for (int k = threadIdx.x; k < NCODES; k += TPB) {
        const float* e = se + k * DIM;
        float s = 0.f;
#pragma unroll
        for (int d = 0; d < DIM; d++) s += e[d] * e[d];
        wee[k] = make_float2(s, sqrtf(ema[k]));
    }
    __syncthreads();

    // balanced token range for this CTA
    size_t start = (size_t)blockIdx.x * (size_t)N / GRID;
    size_t end   = (size_t)(blockIdx.x + 1) * (size_t)N / GRID;

    float lsum = 0.f;

    for (size_t base = start; base < end; base += 2 * TPB) {
        size_t n0 = base + threadIdx.x;
        size_t n1 = n0 + TPB;
        bool vA = n0 < end;
        bool vB = n1 < end;
        size_t a0 = vA ? n0 : start;
        size_t a1 = vB ? n1 : start;

        // load two tokens into registers (packed f32x2 along D)
        unsigned long long xA[DIM / 2], xB[DIM / 2];
        float xxA = 0.f, xxB = 0.f;
        {
            const ulonglong2* pA = (const ulonglong2*)(inputs + a0 * DIM);
            const ulonglong2* pB = (const ulonglong2*)(inputs + a1 * DIM);
#pragma unroll
            for (int j = 0; j < DIM / 4; j++) {
                ulonglong2 va = pA[j];
                ulonglong2 vb = pB[j];
                xA[2 * j] = va.x; xA[2 * j + 1] = va.y;
                xB[2 * j] = vb.x; xB[2 * j + 1] = vb.y;
                float2 a0f = u2f(va.x), a1f = u2f(va.y);
                float2 b0f = u2f(vb.x), b1f = u2f(vb.y);
                xxA += a0f.x * a0f.x + a0f.y * a0f.y + a1f.x * a1f.x + a1f.y * a1f.y;
                xxB += b0f.x * b0f.x + b0f.y * b0f.y + b1f.x * b1f.x + b1f.y * b1f.y;
            }
        }

        float bestA = INFINITY, bestB = INFINITY;
        int kA = 0, kB = 0;

#pragma unroll 1
        for (int k = 0; k < NCODES; k += 2) {
            const ulonglong2* ea = (const ulonglong2*)(se + k * DIM);
            const ulonglong2* eb = ea + DIM / 4;  // next code row
            // 8 independent FMA chains: {tokenA,tokenB} x {code0,code1} x {lo,hi}
            unsigned long long cA0l = 0ull, cA0h = 0ull, cA1l = 0ull, cA1h = 0ull;
            unsigned long long cB0l = 0ull, cB0h = 0ull, cB1l = 0ull, cB1h = 0ull;
#pragma unroll
            for (int j = 0; j < DIM / 4; j++) {
                ulonglong2 v0 = ea[j];      // code k,   floats 4j..4j+3
                ulonglong2 v1 = eb[j];      // code k+1
                cA0l = f32x2_fma(xA[2 * j],     v0.x, cA0l);
                cA0h = f32x2_fma(xA[2 * j + 1], v0.y, cA0h);
                cA1l = f32x2_fma(xA[2 * j],     v1.x, cA1l);
                cA1h = f32x2_fma(xA[2 * j + 1], v1.y, cA1h);
                cB0l = f32x2_fma(xB[2 * j],     v0.x, cB0l);
                cB0h = f32x2_fma(xB[2 * j + 1], v0.y, cB0h);
                cB1l = f32x2_fma(xB[2 * j],     v1.x, cB1l);
                cB1h = f32x2_fma(xB[2 * j + 1], v1.y, cB1h);
            }
            float2 w0 = wee[k];       // (ee_k,   w_k)
            float2 w1 = wee[k + 1];   // (ee_k+1, w_k+1)
            float2 rA0l = u2f(cA0l), rA0h = u2f(cA0h);
            float2 rA1l = u2f(cA1l), rA1h = u2f(cA1h);
            float2 rB0l = u2f(cB0l), rB0h = u2f(cB0h);
            float2 rB1l = u2f(cB1l), rB1h = u2f(cB1h);
            float dA0 = (rA0l.x + rA0l.y) + (rA0h.x + rA0h.y);
            float dA1 = (rA1l.x + rA1l.y) + (rA1h.x + rA1h.y);
            float dB0 = (rB0l.x + rB0l.y) + (rB0h.x + rB0h.y);
            float dB1 = (rB1l.x + rB1l.y) + (rB1h.x + rB1h.y);
            // same op order as reference: (xx + ee - 2*dot) * w
            float tA0 = (xxA + w0.x - 2.0f * dA0) * w0.y;
            float tA1 = (xxA + w1.x - 2.0f * dA1) * w1.y;
            float tB0 = (xxB + w0.x - 2.0f * dB0) * w0.y;
            float tB1 = (xxB + w1.x - 2.0f * dB1) * w1.y;
            if (tA0 < bestA) { bestA = tA0; kA = k; }
            if (tA1 < bestA) { bestA = tA1; kA = k + 1; }
            if (tB0 < bestB) { bestB = tB0; kB = k; }
            if (tB1 < bestB) { bestB = tB1; kB = k + 1; }
        }

        // epilogue: quantized write + loss partial for both tokens
        if (vA) {
            const float2* ep = (const float2*)(se + kA * DIM);
            float2* oq = (float2*)(out_q + n0 * DIM);
#pragma unroll
            for (int j = 0; j < DIM / 2; j++) {
                float2 ev = ep[j];
                float2 xv = u2f(xA[j]);
                float dx = xv.x - ev.x, dy = xv.y - ev.y;
                lsum += dx * dx + dy * dy;
                oq[j] = ev;
            }
            out_idx[n0] = (float)kA;
        }
        if (vB) {
            const float2* ep = (const float2*)(se + kB * DIM);
            float2* oq = (float2*)(out_q + n1 * DIM);
#pragma unroll
            for (int j = 0; j < DIM / 2; j++) {
                float2 ev = ep[j];
                float2 xv = u2f(xB[j]);
                float dx = xv.x - ev.x, dy = xv.y - ev.y;
                lsum += dx * dx + dy * dy;
                oq[j] = ev;
            }
            out_idx[n1] = (float)kB;
        }
    }

    // block reduction of loss partials (reuse smem after barrier)
    __syncthreads();
    float* red = smem;
    red[threadIdx.x] = lsum;
    __syncthreads();
#pragma unroll
    for (int s = TPB / 2; s > 0; s >>= 1) {
        if (threadIdx.x < s) red[threadIdx.x] += red[threadIdx.x + s];
        __syncthreads();
    }
    if (threadIdx.x == 0) g_part[blockIdx.x] = red[0];
}

// ---------- finalize loss ----------
__global__ void vq_finalize(float* __restrict__ out_loss, float inv_count) {
    __shared__ float red[GRID];
    float s = (threadIdx.x < GRID) ? g_part[threadIdx.x] : 0.f;
    red[threadIdx.x % GRID] = 0.f;  // unused slots
    __syncthreads();
    // warp-level tree over 152 values using shfl in a single warp-friendly way:
    // simple smem reduction with 256 threads padded
    __shared__ float buf[256];
    buf[threadIdx.x] = s;
    __syncthreads();
#pragma unroll
    for (int st = 128; st > 0; st >>= 1) {
        if (threadIdx.x < st) buf[threadIdx.x] += buf[threadIdx.x + st];
        __syncthreads();
    }
    if (threadIdx.x == 0) out_loss[0] = 0.25f * buf[0] * inv_count;
}

extern "C" void kernel_launch(void* const* d_in, const int* in_sizes, int n_in,
                              void* d_out, int out_size) {
    const float* inputs = (const float*)d_in[0];   // [B,T,D] f32
    const float* emb    = (const float*)d_in[1];   // [K,D]   f32
    const float* ema    = (const float*)d_in[2];   // [K]     f32

    int N = in_sizes[0] / DIM;                     // 262144
    float* out = (float*)d_out;
    // output layout: quantized_st [N*D], loss [1], indices [N]
    float* out_q    = out;
    float* out_loss = out + (size_t)N * DIM;
    float* out_idx  = out + (size_t)N * DIM + 1;

    size_t smem = (size_t)(NCODES * DIM) * sizeof(float) + NCODES * sizeof(float2);
    static bool attr_done = false;
    if (!attr_done) {
        cudaFuncSetAttribute(vq_main, cudaFuncAttributeMaxDynamicSharedMemorySize,
                             (int)smem);
        attr_done = true;
    }

    vq_main<<<GRID, TPB, smem>>>(inputs, emb, ema, out_q, out_idx, N);
    vq_finalize<<<1, 256>>>(out_loss, 1.0f / ((float)N * (float)DIM));
}